// round 15
// baseline (speedup 1.0000x reference)
#include <cuda_runtime.h>

// Scratch via __device__ globals (no allocations allowed).
__device__ float    g_part[8192];
__device__ unsigned g_count = 0;   // self-resetting ticket -> deterministic per call

// MUFU sqrt: single instruction, max rel err ~2^-23, sqrt(0)=0.
__device__ __forceinline__ float fsqrt_approx(float x) {
    float r;
    asm("sqrt.approx.f32 %0, %1;" : "=f"(r) : "f"(x));
    return r;
}

// Shapes fixed: [8,3,16,256,256] fp32 -> 384 planes of 256x256. Row = 64 float4.
// FULL-ROW WARPS + ROLLING WINDOW + SMEM BOUNDARY-ROW SHARING:
//  - one warp covers a complete 256-wide row per step (lane l holds u=row[q=l],
//    v=row[q=l+32]; two 512B-coalesced LDG.128 per row).
//  - circular x-wraps are intra-warp shuffles only (q31.w->q32.x = v.x lane 0;
//    q63.w->q0.x = u.x lane 0) -> zero divergent scalar loads.
//  - a block's 8 warps cover 64 CONSECUTIVE rows; each warp stores its first
//    row to SMEM, so warps 0-6 take their last c-row (= next warp's first row)
//    from SMEM instead of L2. Only warp 7 loads one extra global row.
//    L2 traffic drops from 72 to 65 rows/block (1.125x -> 1.016x) — attacks
//    the chip-wide LTS throughput cap that R10/R14 both sit on (~6.1 TB/s).
//  - __launch_bounds__(256,8): 32-reg pin, 8 blocks/SM, 8KB SMEM each.
// TV magnitude: sqrt((x[h,w]-x[h,w+1])^2 + (x[h,w]-x[h+1,w])^2), circular.
__global__ void __launch_bounds__(256, 8) tv_fused_kernel(const float4* __restrict__ in4,
                                                          float* __restrict__ out,
                                                          double inv_n) {
    const unsigned FULL = 0xFFFFFFFFu;
    const int lane = threadIdx.x & 31;
    const int wid  = threadIdx.x >> 5;
    const int plane = blockIdx.x >> 2;        // 4 blocks per 256x256 plane
    const int H0    = (blockIdx.x & 3) << 6;  // block's 64-row window
    const int h0    = H0 + (wid << 3);        // this warp's 8-row strip

    const float4* __restrict__ p4 = in4 + ((long)plane << 14);  // 16384 float4/plane

    __shared__ float4 srow[8][64];            // each warp's FIRST row (8 KB)
    __shared__ float  warpsum[8];
    __shared__ bool   s_last;

    // Load first row (h0) and publish it for the warp below.
    const int rb0 = h0 << 6;
    float4 uc = p4[rb0 + lane];
    float4 vc = p4[rb0 + 32 + lane];
    srow[wid][lane]      = uc;
    srow[wid][32 + lane] = vc;
    if (threadIdx.x == 0) s_last = false;
    __syncthreads();

    float acc = 0.0f;
    #pragma unroll
    for (int i = 0; i < 8; i++) {
        // c-row (row h0+i+1): global for i<7; for i==7 it's the next warp's
        // first row -> SMEM (warps 0-6) or one global load (warp 7, circular).
        float4 un, vn;
        if (i < 7) {
            const int rbn = (h0 + i + 1) << 6;            // h0+7 <= 255, no wrap
            un = p4[rbn + lane];
            vn = p4[rbn + 32 + lane];
        } else if (wid < 7) {
            un = srow[wid + 1][lane];
            vn = srow[wid + 1][32 + lane];
        } else {
            const int rbn = ((h0 + 8) & 255) << 6;        // circular (plane wrap)
            un = p4[rbn + lane];
            vn = p4[rbn + 32 + lane];
        }

        // Circular x-neighbors via shuffle (all lanes execute both).
        const float su  = __shfl_down_sync(FULL, uc.x, 1);
        const float sv0 = __shfl_sync(FULL, vc.x, 0);
        const float nu  = (lane == 31) ? sv0 : su;
        const float sv  = __shfl_down_sync(FULL, vc.x, 1);
        const float su0 = __shfl_sync(FULL, uc.x, 0);
        const float nv  = (lane == 31) ? su0 : sv;

        #define TV_PROC(a, nxt, c)                                         \
        {                                                                  \
            float dx0 = a.x - a.y,   dy0 = a.x - c.x;                      \
            float dx1 = a.y - a.z,   dy1 = a.y - c.y;                      \
            float dx2 = a.z - a.w,   dy2 = a.z - c.z;                      \
            float dx3 = a.w - (nxt), dy3 = a.w - c.w;                      \
            acc += fsqrt_approx(fmaf(dx0, dx0, dy0 * dy0));                \
            acc += fsqrt_approx(fmaf(dx1, dx1, dy1 * dy1));                \
            acc += fsqrt_approx(fmaf(dx2, dx2, dy2 * dy2));                \
            acc += fsqrt_approx(fmaf(dx3, dx3, dy3 * dy3));                \
        }
        TV_PROC(uc, nu, un)
        TV_PROC(vc, nv, vn)
        #undef TV_PROC

        uc = un; vc = vn;
    }

    // Warp reduce (8 warps per block)
    #pragma unroll
    for (int o = 16; o > 0; o >>= 1)
        acc += __shfl_xor_sync(FULL, acc, o);

    if (lane == 0) warpsum[wid] = acc;
    __syncthreads();

    if (threadIdx.x == 0) {
        float bsum = warpsum[0] + warpsum[1] + warpsum[2] + warpsum[3]
                   + warpsum[4] + warpsum[5] + warpsum[6] + warpsum[7];
        g_part[blockIdx.x] = bsum;
        __threadfence();
        unsigned ticket = atomicAdd(&g_count, 1u);
        if (ticket == gridDim.x - 1) s_last = true;
    }
    __syncthreads();

    // Last block to arrive reduces all partials and writes the output.
    if (s_last) {
        double dsum = 0.0;
        for (int i = threadIdx.x; i < (int)gridDim.x; i += 256)
            dsum += (double)g_part[i];
        #pragma unroll
        for (int o = 16; o > 0; o >>= 1)
            dsum += __shfl_xor_sync(FULL, dsum, o);
        __shared__ double dws[8];
        if (lane == 0) dws[wid] = dsum;
        __syncthreads();
        if (threadIdx.x == 0) {
            double ssum = dws[0] + dws[1] + dws[2] + dws[3]
                        + dws[4] + dws[5] + dws[6] + dws[7];
            out[0] = (float)(ssum * inv_n);
            g_count = 0;   // reset for next (graph-replayed) call
        }
    }
}

extern "C" void kernel_launch(void* const* d_in, const int* in_sizes, int n_in,
                              void* d_out, int out_size) {
    const float4* in4 = (const float4*)d_in[0];
    float* out = (float*)d_out;
    const long long n = in_sizes[0];              // 25,165,824
    // 384 planes * 4 blocks/plane = 1536 blocks of 8 warps (64 rows per block)
    const int threads = 256;
    const int blocks  = (int)(n / (threads * 64));  // 64 elems per thread -> 1536

    tv_fused_kernel<<<blocks, threads>>>(in4, out, 1.0 / (double)n);
}

// round 16
// speedup vs baseline: 1.0307x; 1.0307x over previous
#include <cuda_runtime.h>

// Scratch via __device__ globals (no allocations allowed).
__device__ float    g_part[8192];
__device__ unsigned g_count = 0;   // self-resetting ticket -> deterministic per call

// MUFU sqrt: single instruction, max rel err ~2^-23, sqrt(0)=0.
__device__ __forceinline__ float fsqrt_approx(float x) {
    float r;
    asm("sqrt.approx.f32 %0, %1;" : "=f"(r) : "f"(x));
    return r;
}

// Shapes fixed: [8,3,16,256,256] fp32 -> 384 planes of 256x256. Row = 64 float4.
// FULL-ROW WARPS + ROLLING WINDOW (R10 geometry) + DUAL ACCUMULATORS:
//  - one warp covers a complete 256-wide row per step (lane l holds u=row[q=l],
//    v=row[q=l+32]; two 512B-coalesced LDG.128 per row).
//  - circular x-wraps are intra-warp shuffles only (q31.w->q32.x = v.x lane 0;
//    q63.w->q0.x = u.x lane 0) -> zero divergent scalar loads.
//  - rolling 1-row-ahead window; ~32 regs -> 8 blocks/SM, occ ~83%.
//  - TWO independent accumulators (u-half / v-half) halve the serial
//    FADD(lat4)<-MUFU(lat16) spine that the flat R10/R14/R15 frontier
//    identified as the remaining latency residue.
// TV magnitude: sqrt((x[h,w]-x[h,w+1])^2 + (x[h,w]-x[h+1,w])^2), circular.
__global__ void __launch_bounds__(256, 8) tv_fused_kernel(const float4* __restrict__ in4,
                                                          float* __restrict__ out,
                                                          double inv_n) {
    const unsigned FULL = 0xFFFFFFFFu;
    const int lane = threadIdx.x & 31;
    const int wid  = threadIdx.x >> 5;
    const int gw   = blockIdx.x * 8 + wid;    // global warp id
    const int plane = gw >> 5;                // 32 strips per 256x256 plane
    const int h0    = (gw & 31) << 3;         // first row of this warp's 8-row strip

    const float4* __restrict__ p4 = in4 + ((long)plane << 14);  // 16384 float4/plane

    // Current row (h0)
    const int rb0 = h0 << 6;
    float4 uc = p4[rb0 + lane];
    float4 vc = p4[rb0 + 32 + lane];

    float acc0 = 0.0f, acc1 = 0.0f;
    #pragma unroll
    for (int i = 0; i < 8; i++) {
        // Issue next-row loads FIRST (independent of current compute).
        const int rbn = (((h0 + i + 1) & 255) << 6);   // wraps only for last strip
        const float4 un = p4[rbn + lane];
        const float4 vn = p4[rbn + 32 + lane];

        // Circular x-neighbors via shuffle (all lanes execute both).
        const float su  = __shfl_down_sync(FULL, uc.x, 1);
        const float sv0 = __shfl_sync(FULL, vc.x, 0);
        const float nu  = (lane == 31) ? sv0 : su;
        const float sv  = __shfl_down_sync(FULL, vc.x, 1);
        const float su0 = __shfl_sync(FULL, uc.x, 0);
        const float nv  = (lane == 31) ? su0 : sv;

        // Interleaved dual-chain compute: u-half -> acc0, v-half -> acc1.
        {
            float udx0 = uc.x - uc.y, udy0 = uc.x - un.x;
            float vdx0 = vc.x - vc.y, vdy0 = vc.x - vn.x;
            float udx1 = uc.y - uc.z, udy1 = uc.y - un.y;
            float vdx1 = vc.y - vc.z, vdy1 = vc.y - vn.y;
            float udx2 = uc.z - uc.w, udy2 = uc.z - un.z;
            float vdx2 = vc.z - vc.w, vdy2 = vc.z - vn.z;
            float udx3 = uc.w - nu,   udy3 = uc.w - un.w;
            float vdx3 = vc.w - nv,   vdy3 = vc.w - vn.w;

            acc0 += fsqrt_approx(fmaf(udx0, udx0, udy0 * udy0));
            acc1 += fsqrt_approx(fmaf(vdx0, vdx0, vdy0 * vdy0));
            acc0 += fsqrt_approx(fmaf(udx1, udx1, udy1 * udy1));
            acc1 += fsqrt_approx(fmaf(vdx1, vdx1, vdy1 * vdy1));
            acc0 += fsqrt_approx(fmaf(udx2, udx2, udy2 * udy2));
            acc1 += fsqrt_approx(fmaf(vdx2, vdx2, vdy2 * vdy2));
            acc0 += fsqrt_approx(fmaf(udx3, udx3, udy3 * udy3));
            acc1 += fsqrt_approx(fmaf(vdx3, vdx3, vdy3 * vdy3));
        }

        uc = un; vc = vn;
    }
    float acc = acc0 + acc1;

    // Warp reduce (8 warps per block)
    #pragma unroll
    for (int o = 16; o > 0; o >>= 1)
        acc += __shfl_xor_sync(FULL, acc, o);

    __shared__ float warpsum[8];
    __shared__ bool  s_last;
    if (lane == 0) warpsum[wid] = acc;
    if (threadIdx.x == 0) s_last = false;
    __syncthreads();

    if (threadIdx.x == 0) {
        float bsum = warpsum[0] + warpsum[1] + warpsum[2] + warpsum[3]
                   + warpsum[4] + warpsum[5] + warpsum[6] + warpsum[7];
        g_part[blockIdx.x] = bsum;
        __threadfence();
        unsigned ticket = atomicAdd(&g_count, 1u);
        if (ticket == gridDim.x - 1) s_last = true;
    }
    __syncthreads();

    // Last block to arrive reduces all partials and writes the output.
    if (s_last) {
        double dsum = 0.0;
        for (int i = threadIdx.x; i < (int)gridDim.x; i += 256)
            dsum += (double)g_part[i];
        #pragma unroll
        for (int o = 16; o > 0; o >>= 1)
            dsum += __shfl_xor_sync(FULL, dsum, o);
        __shared__ double dws[8];
        if (lane == 0) dws[wid] = dsum;
        __syncthreads();
        if (threadIdx.x == 0) {
            double ssum = dws[0] + dws[1] + dws[2] + dws[3]
                        + dws[4] + dws[5] + dws[6] + dws[7];
            out[0] = (float)(ssum * inv_n);
            g_count = 0;   // reset for next (graph-replayed) call
        }
    }
}

extern "C" void kernel_launch(void* const* d_in, const int* in_sizes, int n_in,
                              void* d_out, int out_size) {
    const float4* in4 = (const float4*)d_in[0];
    float* out = (float*)d_out;
    const long long n = in_sizes[0];              // 25,165,824
    // 384 planes * 32 strips/plane = 12288 warps = 1536 blocks of 8 warps
    const int threads = 256;
    const int blocks  = (int)(n / (threads * 64));  // 64 elems per thread -> 1536

    tv_fused_kernel<<<blocks, threads>>>(in4, out, 1.0 / (double)n);
}